// round 15
// baseline (speedup 1.0000x reference)
#include <cuda_runtime.h>
#include <cuda_fp16.h>
#include <stdint.h>

#define DI __device__ __forceinline__
#define N_NODES 8192
#define F_OUT   256
#define F_IN    512
#define K1      1024   // 2-segment split-fp16 GEMM1 (W side)

__device__ __align__(16) __half g_xh[(size_t)N_NODES * 512];     // x_hi (single copy)
__device__ __align__(16) __half g_wt[(size_t)F_OUT * K1];        // [W_hi | W_lo] (transposed)
__device__ __align__(16) float  g_hp[2ull * N_NODES * F_OUT];    // split-K partials
__device__ __align__(16) __half g_wht[(size_t)F_OUT * N_NODES];
__device__ __align__(16) float  g_b[N_NODES];
__device__ __align__(16) float  g_w[N_NODES];
__device__ __align__(16) float  g_den[2 * N_NODES];
__device__ float g_u[F_IN];
__device__ float g_c;

extern __shared__ __align__(16) char dynsm[];

DI uint32_t sm_u32(const void* p){ return (uint32_t)__cvta_generic_to_shared(p); }
DI void cp16(uint32_t d, const void* s){ asm volatile("cp.async.cg.shared.global [%0],[%1],16;\n"::"r"(d),"l"(s)); }
DI void cpcommit(){ asm volatile("cp.async.commit_group;\n":::"memory"); }
template<int N> DI void cpwaitg(){ asm volatile("cp.async.wait_group %0;\n"::"n"(N):"memory"); }

DI void mma16816(float* c, const uint32_t* a, uint32_t b0, uint32_t b1){
  asm volatile("mma.sync.aligned.m16n8k16.row.col.f32.f16.f16.f32 "
    "{%0,%1,%2,%3},{%4,%5,%6,%7},{%8,%9},{%0,%1,%2,%3};\n"
    : "+f"(c[0]),"+f"(c[1]),"+f"(c[2]),"+f"(c[3])
    : "r"(a[0]),"r"(a[1]),"r"(a[2]),"r"(a[3]),"r"(b0),"r"(b1));
}
DI void ldsm4(uint32_t* r, uint32_t a){
  asm volatile("ldmatrix.sync.aligned.m8n8.x4.shared.b16 {%0,%1,%2,%3},[%4];"
    : "=r"(r[0]),"=r"(r[1]),"=r"(r[2]),"=r"(r[3]) : "r"(a));
}

// Warp tile 64(m) x 32(n), frag double-buffered across 4 kk-steps.
// Shared rows: 64 halves (128B) = 8 x 16B chunks, chunk XOR (row&7) swizzle.
DI void mma_tileW(uint32_t Asb, uint32_t Bsb, float (&acc)[4][4][4],
                  int wm, int wn, int lane){
  const int la7 = lane & 7;
  const int a_row0 = wm*64 + (lane & 8) + la7;
  const uint32_t ca0 = (uint32_t)(lane >> 4);
  const int b_row0 = wn*32 + ((lane >> 4) << 3) + la7;
  const uint32_t cb0 = (uint32_t)((lane >> 3) & 1);
  uint32_t a[2][4][4], b[2][2][4];
#pragma unroll
  for (int mi=0; mi<4; mi++){
    int r = a_row0 + mi*16;
    ldsm4(a[0][mi], Asb + r*128 + ((ca0 ^ (uint32_t)(r&7)) << 4));
  }
#pragma unroll
  for (int nj=0; nj<2; nj++){
    int r = b_row0 + nj*16;
    ldsm4(b[0][nj], Bsb + r*128 + ((cb0 ^ (uint32_t)(r&7)) << 4));
  }
#pragma unroll
  for (int kk=0; kk<4; kk++){
    const int cur = kk&1, nxt = cur^1;
    if (kk < 3){
      const uint32_t cau = (uint32_t)((kk+1)<<1) | ca0;
      const uint32_t cbu = (uint32_t)((kk+1)<<1) | cb0;
#pragma unroll
      for (int mi=0; mi<4; mi++){
        int r = a_row0 + mi*16;
        ldsm4(a[nxt][mi], Asb + r*128 + ((cau ^ (uint32_t)(r&7)) << 4));
      }
#pragma unroll
      for (int nj=0; nj<2; nj++){
        int r = b_row0 + nj*16;
        ldsm4(b[nxt][nj], Bsb + r*128 + ((cbu ^ (uint32_t)(r&7)) << 4));
      }
    }
#pragma unroll
    for (int mi=0; mi<4; mi++){
      mma16816(acc[mi][0], a[cur][mi], b[cur][0][0], b[cur][0][1]);
      mma16816(acc[mi][1], a[cur][mi], b[cur][0][2], b[cur][0][3]);
      mma16816(acc[mi][2], a[cur][mi], b[cur][1][0], b[cur][1][1]);
      mma16816(acc[mi][3], a[cur][mi], b[cur][1][2], b[cur][1][3]);
    }
  }
}

// ---------------- pre-kernels ----------------
__global__ void k_conv(const float* __restrict__ x, const float* __restrict__ wgt){
  if (blockIdx.x < 4096){
    int idx = blockIdx.x*256 + threadIdx.x;     // float4 index
    float4 v = ((const float4*)x)[idx];
    ((__half2*)g_xh)[idx*2]   = __floats2half2_rn(v.x, v.y);
    ((__half2*)g_xh)[idx*2+1] = __floats2half2_rn(v.z, v.w);
  } else {
    int idx = (blockIdx.x-4096)*256 + threadIdx.x;
    int k = idx >> 8, f = idx & 255;
    float v = wgt[idx];
    __half hi = __float2half_rn(v);
    __half lo = __float2half_rn(v - __half2float(hi));
    size_t base = (size_t)f*K1 + k;
    g_wt[base] = hi; g_wt[base+512] = lo;
  }
}
__global__ void k_ucc(const float* __restrict__ wgt, const float* __restrict__ bias,
                      const float* __restrict__ phi){
  int gw = (blockIdx.x*256 + threadIdx.x) >> 5;
  int lane = threadIdx.x & 31;
  if (gw < F_IN){
    float s = 0.f;
#pragma unroll
    for (int i=0;i<8;i++){ int f=i*32+lane; s += wgt[gw*256+f]*phi[256+f]; }
    for (int o=16;o;o>>=1) s += __shfl_down_sync(0xFFFFFFFFu, s, o);
    if (!lane) g_u[gw] = s;
  } else if (gw == F_IN){
    float s = 0.f;
#pragma unroll
    for (int i=0;i<8;i++){ int f=i*32+lane; s += bias[f]*phi[256+f]; }
    for (int o=16;o;o>>=1) s += __shfl_down_sync(0xFFFFFFFFu, s, o);
    if (!lane) g_c = s;
  }
}
__global__ void k_bvec(const float* __restrict__ x){
  __shared__ float su[F_IN];
  for (int i=threadIdx.x; i<F_IN; i+=256) su[i] = g_u[i];
  __syncthreads();
  int row = blockIdx.x*8 + (threadIdx.x >> 5);
  int lane = threadIdx.x & 31;
  const float* xr = x + (size_t)row*F_IN;
  float s = 0.f;
#pragma unroll
  for (int i=0;i<16;i++){ int k=i*32+lane; s += xr[k]*su[k]; }
  for (int o=16;o;o>>=1) s += __shfl_down_sync(0xFFFFFFFFu, s, o);
  if (!lane) g_b[row] = s + g_c;
}
__global__ void k_maxw(){
  __shared__ float s[1024];
  int t = threadIdx.x;
  float m = -3.4e38f;
  for (int i=t; i<N_NODES; i+=1024) m = fmaxf(m, g_b[i]);
  s[t] = m; __syncthreads();
  for (int o=512;o;o>>=1){ if (t<o) s[t]=fmaxf(s[t],s[t+o]); __syncthreads(); }
  float gm = s[0];
  for (int i=t; i<N_NODES; i+=1024) g_w[i] = expf(g_b[i] - gm);
}
__global__ void k_wht(const float* __restrict__ bias){
  __shared__ float s[32][33];
  int j0 = blockIdx.x*32, f0 = blockIdx.y*32;
  int tx = threadIdx.x & 31, ty = threadIdx.x >> 5;
  float bv = bias[f0+tx];
#pragma unroll
  for (int q=0;q<4;q++){
    size_t o = (size_t)(j0+ty+8*q)*F_OUT + f0+tx;
    s[ty+8*q][tx] = g_hp[o] + g_hp[o + (size_t)N_NODES*F_OUT] + bv;
  }
  __syncthreads();
  float wj = g_w[j0+tx];
#pragma unroll
  for (int q=0;q<4;q++)
    g_wht[(size_t)(f0+ty+8*q)*N_NODES + j0+tx] = __float2half_rn(wj * s[tx][ty+8*q]);
}
__global__ void k_epi(float* __restrict__ out){
  int i = blockIdx.x, t = threadIdx.x;
  float inv = 1.f / (g_den[i] + g_den[N_NODES + i]);
  size_t o = (size_t)i*F_OUT + t;
  out[o] = fmaxf((g_hp[o] + g_hp[o + (size_t)N_NODES*F_OUT]) * inv, 0.f);
}

// ---------------- GEMM1 (BM=128, split-K x2, 4-stage, per-ktile fills; R14 shape) ----------------
__global__ void __launch_bounds__(512) k_gemm1(){
  const uint32_t Asb = sm_u32(dynsm);            // 4 * 16384
  const uint32_t Bsb = Asb + 65536;              // 4 * 32768
  const int t = threadIdx.x, bm = blockIdx.x & 63, kh = blockIdx.x >> 6;
  const int warp = t>>5, lane = t&31, wm = warp&1, wn = warp>>1, g = lane>>2, tg = lane&3;
  float acc[4][4][4] = {};
  const int KT = 8;
  const int ar0 = t>>3, ac0 = t&7;
  const int ar1 = (t+512)>>3, ac1 = (t+512)&7;
  const int br = t>>1, bc0 = (t&1)*4;
  auto fill = [&](int s, int kt){
    cp16(Asb + s*16384 + ar0*128 + ((ac0^(ar0&7))<<4),
         g_xh + (size_t)(bm*128+ar0)*512 + kt*64 + ac0*8);
    cp16(Asb + s*16384 + ar1*128 + ((ac1^(ar1&7))<<4),
         g_xh + (size_t)(bm*128+ar1)*512 + kt*64 + ac1*8);
    const __half* bsrc = g_wt + (size_t)br*K1 + kh*512 + kt*64;
#pragma unroll
    for (int i=0;i<4;i++)
      cp16(Bsb + s*32768 + br*128 + (((bc0+i)^(br&7))<<4), bsrc + (bc0+i)*8);
  };
  fill(0,0); cpcommit();
  fill(1,1); cpcommit();
  for (int kt=0; kt<KT; kt++){
    if (kt+2 < KT){ fill((kt+2)&3, kt+2); cpcommit(); cpwaitg<2>(); }
    else cpwaitg<0>();
    __syncthreads();
    int s = kt&3;
    mma_tileW(Asb + s*16384, Bsb + s*32768, acc, wm, wn, lane);
  }
  float* hp = g_hp + (size_t)kh*N_NODES*F_OUT;
#pragma unroll
  for (int mi=0; mi<4; mi++)
#pragma unroll
    for (int ni=0; ni<4; ni++){
      int r = wm*64 + mi*16 + g, c = wn*32 + ni*8 + tg*2;
      size_t go = (size_t)(bm*128+r)*F_OUT + c;
      *(float2*)(hp+go)         = make_float2(acc[mi][ni][0], acc[mi][ni][1]);
      *(float2*)(hp+go+8*F_OUT) = make_float2(acc[mi][ni][2], acc[mi][ni][3]);
    }
}

// ---------------- GEMM2 (BM=64, 256 thr, 2 CTAs/SM, split-K x2) ----------------
// grid 256: bm = bid&127 (64 rows), kh = bid>>7 (4096-wide K half, 64 ktiles)
// smem/CTA: A mask 2x8KB @0 | B 3x32KB @16384 = 114688 B  => 2 CTAs resident
__global__ void __launch_bounds__(256,2) k_gemm2(const int* __restrict__ adj){
  const uint32_t Asb = sm_u32(dynsm);
  const uint32_t Bsb = Asb + 16384;
  const int t = threadIdx.x, bm = blockIdx.x & 127, kh = blockIdx.x >> 7;
  const int warp = t>>5, lane = t&31, g = lane>>2, tg = lane&3;
  float acc[4][4][4] = {};
  float dpart[4] = {0.f,0.f,0.f,0.f};
  const int khoff = kh*4096;
  // B: thread t owns row t (8 chunks)
  auto fillB = [&](int s, int kt){
    const __half* bsrc = g_wht + (size_t)t*N_NODES + khoff + kt*64;
#pragma unroll
    for (int i=0;i<8;i++)
      cp16(Bsb + s*32768 + t*128 + ((i^(t&7))<<4), bsrc + i*8);
  };
  // A slots: 64 rows x 16 int4 = 1024, 4/thread
  int row_[4], c4_[4], gi_[4];
  const int4* aptr[4];
  uint32_t hdst[4];
#pragma unroll
  for (int i=0;i<4;i++){
    int slot = t + i*256;
    row_[i] = slot >> 4; c4_[i] = slot & 15;
    gi_[i] = bm*64 + row_[i];
    aptr[i] = (const int4*)(adj + (size_t)gi_[i]*N_NODES + khoff) + c4_[i];
    hdst[i] = Asb + row_[i]*128 + (((c4_[i]>>1) ^ (row_[i]&7)) << 4) + (c4_[i]&1)*8;
  }
  int4 av[4];
  auto ldav = [&](int c){
#pragma unroll
    for (int i=0;i<4;i++) av[i] = aptr[i][c*16];
  };
  auto buildA = [&](int s, int c){
#pragma unroll
    for (int i=0;i<4;i++){
      int j = khoff + c*64 + c4_[i]*4;
      int4 a = av[i];
      int m0 = (a.x!=0) | (gi_[i]==j);
      int m1 = (a.y!=0) | (gi_[i]==j+1);
      int m2 = (a.z!=0) | (gi_[i]==j+2);
      int m3 = (a.w!=0) | (gi_[i]==j+3);
      float4 wv = *(const float4*)(g_w + khoff + c*64 + c4_[i]*4);  // L2-hot
      dpart[i] += (m0?wv.x:0.f) + (m1?wv.y:0.f) + (m2?wv.z:0.f) + (m3?wv.w:0.f);
      uint32_t u0 = (m0 ? 0x3C00u : 0u) | (m1 ? 0x3C000000u : 0u);
      uint32_t u1 = (m2 ? 0x3C00u : 0u) | (m3 ? 0x3C000000u : 0u);
      asm volatile("st.shared.v2.b32 [%0], {%1,%2};" :: "r"(hdst[i] + s*8192), "r"(u0), "r"(u1));
    }
  };
  const int KT = 64;
  ldav(0); buildA(0, 0);          // A stage 0 (no concurrent readers yet)
  ldav(1);
  fillB(0,0); cpcommit();
  fillB(1,1); cpcommit();
  for (int kt=0; kt<KT; kt++){
    __syncthreads();                    // retire mma(kt-1): A stage (kt+1)&1 and B stage (kt+2)%3 now writable
    if (kt+2 < KT) fillB((kt+2)%3, kt+2);
    if (kt+1 < KT){
      buildA((kt+1)&1, kt+1);
      if (kt+2 < KT) ldav(kt+2);        // adj LDG lands under mma(kt)
    }
    cpcommit();
    cpwaitg<2>();                       // fill(kt) complete (2 newest groups may remain)
    __syncthreads();                    // publish fill(kt) + buildA(kt) to all warps
    mma_tileW(Asb + (kt&1)*8192, Bsb + (kt%3)*32768, acc, 0, warp, lane);
  }
  // denominator reduction in A region (mma done)
  __syncthreads();
  float* sred = (float*)dynsm;          // slot = row*16 + c4
#pragma unroll
  for (int i=0;i<4;i++) sred[t + i*256] = dpart[i];
  __syncthreads();
  if (t < 64){
    float s = 0.f;
#pragma unroll
    for (int q=0;q<16;q++) s += sred[t*16+q];
    g_den[kh*N_NODES + bm*64 + t] = s;
  }
  float* hp = g_hp + (size_t)kh*N_NODES*F_OUT;
#pragma unroll
  for (int mi=0; mi<4; mi++)
#pragma unroll
    for (int ni=0; ni<4; ni++){
      int r = mi*16 + g, c = warp*32 + ni*8 + tg*2;
      size_t go = (size_t)(bm*64+r)*F_OUT + c;
      *(float2*)(hp+go)         = make_float2(acc[mi][ni][0], acc[mi][ni][1]);
      *(float2*)(hp+go+8*F_OUT) = make_float2(acc[mi][ni][2], acc[mi][ni][3]);
    }
}

extern "C" void kernel_launch(void* const* d_in, const int* in_sizes, int n_in,
                              void* d_out, int out_size){
  const int*   adj  = (const int*)d_in[0];
  const float* x    = (const float*)d_in[1];
  const float* wgt  = (const float*)d_in[2];
  const float* bias = (const float*)d_in[3];
  const float* phi  = (const float*)d_in[4];
  float* out = (float*)d_out;
  cudaFuncSetAttribute(k_gemm1, cudaFuncAttributeMaxDynamicSharedMemorySize, 196608);
  cudaFuncSetAttribute(k_gemm2, cudaFuncAttributeMaxDynamicSharedMemorySize, 114688);
  k_conv<<<4608, 256>>>(x, wgt);              // 1
  k_ucc<<<65, 256>>>(wgt, bias, phi);         // 2
  k_bvec<<<N_NODES/8, 256>>>(x);              // 3
  k_gemm1<<<128, 512, 196608>>>();            // 4  <- ncu capture slot
  k_maxw<<<1, 1024>>>();                      // 5
  k_wht<<<dim3(256,8), 256>>>(bias);          // 6
  k_gemm2<<<256, 256, 114688>>>(adj);         // 7
  k_epi<<<N_NODES, 256>>>(out);               // 8
}

// round 16
// speedup vs baseline: 1.4613x; 1.4613x over previous
#include <cuda_runtime.h>
#include <cuda_fp16.h>
#include <stdint.h>

#define DI __device__ __forceinline__
#define N_NODES 8192
#define F_OUT   256
#define F_IN    512
#define K1      1024   // 2-segment split-fp16 GEMM1 (W side)

__device__ __align__(16) __half g_xh[(size_t)N_NODES * 512];     // x_hi (single copy)
__device__ __align__(16) __half g_wt[(size_t)F_OUT * K1];        // [W_hi | W_lo] (transposed)
__device__ __align__(16) float  g_hp[2ull * N_NODES * F_OUT];    // split-K partials
__device__ __align__(16) __half g_wht[(size_t)F_OUT * N_NODES];
__device__ __align__(16) float  g_b[N_NODES];
__device__ __align__(16) float  g_w[N_NODES];
__device__ __align__(16) float  g_den[2 * N_NODES];
__device__ float g_u[F_IN];
__device__ float g_c;

extern __shared__ __align__(16) char dynsm[];

DI uint32_t sm_u32(const void* p){ return (uint32_t)__cvta_generic_to_shared(p); }
DI void cp16(uint32_t d, const void* s){ asm volatile("cp.async.cg.shared.global [%0],[%1],16;\n"::"r"(d),"l"(s)); }
DI void cpcommit(){ asm volatile("cp.async.commit_group;\n":::"memory"); }
template<int N> DI void cpwaitg(){ asm volatile("cp.async.wait_group %0;\n"::"n"(N):"memory"); }

DI void mma16816(float* c, const uint32_t* a, uint32_t b0, uint32_t b1){
  asm volatile("mma.sync.aligned.m16n8k16.row.col.f32.f16.f16.f32 "
    "{%0,%1,%2,%3},{%4,%5,%6,%7},{%8,%9},{%0,%1,%2,%3};\n"
    : "+f"(c[0]),"+f"(c[1]),"+f"(c[2]),"+f"(c[3])
    : "r"(a[0]),"r"(a[1]),"r"(a[2]),"r"(a[3]),"r"(b0),"r"(b1));
}
DI void ldsm4(uint32_t* r, uint32_t a){
  asm volatile("ldmatrix.sync.aligned.m8n8.x4.shared.b16 {%0,%1,%2,%3},[%4];"
    : "=r"(r[0]),"=r"(r[1]),"=r"(r[2]),"=r"(r[3]) : "r"(a));
}

// Block tile 128(m) x 256(n) x 64(k); 16 warps = 2(m) x 8(n); warp tile 64x32.
// Shared rows: 64 halves (128B) = 8 x 16B chunks, chunk XOR (row&7) swizzle.
// Fragments double-buffered across the 4 kk-steps.
DI void mma_tileW(uint32_t Asb, uint32_t Bsb, float (&acc)[4][4][4],
                  int wm, int wn, int lane){
  const int la7 = lane & 7;
  const int a_row0 = wm*64 + (lane & 8) + la7;
  const uint32_t ca0 = (uint32_t)(lane >> 4);
  const int b_row0 = wn*32 + ((lane >> 4) << 3) + la7;
  const uint32_t cb0 = (uint32_t)((lane >> 3) & 1);
  uint32_t a[2][4][4], b[2][2][4];
#pragma unroll
  for (int mi=0; mi<4; mi++){
    int r = a_row0 + mi*16;
    ldsm4(a[0][mi], Asb + r*128 + ((ca0 ^ (uint32_t)(r&7)) << 4));
  }
#pragma unroll
  for (int nj=0; nj<2; nj++){
    int r = b_row0 + nj*16;
    ldsm4(b[0][nj], Bsb + r*128 + ((cb0 ^ (uint32_t)(r&7)) << 4));
  }
#pragma unroll
  for (int kk=0; kk<4; kk++){
    const int cur = kk&1, nxt = cur^1;
    if (kk < 3){
      const uint32_t cau = (uint32_t)((kk+1)<<1) | ca0;
      const uint32_t cbu = (uint32_t)((kk+1)<<1) | cb0;
#pragma unroll
      for (int mi=0; mi<4; mi++){
        int r = a_row0 + mi*16;
        ldsm4(a[nxt][mi], Asb + r*128 + ((cau ^ (uint32_t)(r&7)) << 4));
      }
#pragma unroll
      for (int nj=0; nj<2; nj++){
        int r = b_row0 + nj*16;
        ldsm4(b[nxt][nj], Bsb + r*128 + ((cbu ^ (uint32_t)(r&7)) << 4));
      }
    }
#pragma unroll
    for (int mi=0; mi<4; mi++){
      mma16816(acc[mi][0], a[cur][mi], b[cur][0][0], b[cur][0][1]);
      mma16816(acc[mi][1], a[cur][mi], b[cur][0][2], b[cur][0][3]);
      mma16816(acc[mi][2], a[cur][mi], b[cur][1][0], b[cur][1][1]);
      mma16816(acc[mi][3], a[cur][mi], b[cur][1][2], b[cur][1][3]);
    }
  }
}

// ---------------- pre-kernels ----------------
__global__ void k_conv(const float* __restrict__ x, const float* __restrict__ wgt){
  if (blockIdx.x < 4096){
    int idx = blockIdx.x*256 + threadIdx.x;     // float4 index
    float4 v = ((const float4*)x)[idx];
    ((__half2*)g_xh)[idx*2]   = __floats2half2_rn(v.x, v.y);
    ((__half2*)g_xh)[idx*2+1] = __floats2half2_rn(v.z, v.w);
  } else {
    int idx = (blockIdx.x-4096)*256 + threadIdx.x;
    int k = idx >> 8, f = idx & 255;
    float v = wgt[idx];
    __half hi = __float2half_rn(v);
    __half lo = __float2half_rn(v - __half2float(hi));
    size_t base = (size_t)f*K1 + k;
    g_wt[base] = hi; g_wt[base+512] = lo;
  }
}
__global__ void k_ucc(const float* __restrict__ wgt, const float* __restrict__ bias,
                      const float* __restrict__ phi){
  int gw = (blockIdx.x*256 + threadIdx.x) >> 5;
  int lane = threadIdx.x & 31;
  if (gw < F_IN){
    float s = 0.f;
#pragma unroll
    for (int i=0;i<8;i++){ int f=i*32+lane; s += wgt[gw*256+f]*phi[256+f]; }
    for (int o=16;o;o>>=1) s += __shfl_down_sync(0xFFFFFFFFu, s, o);
    if (!lane) g_u[gw] = s;
  } else if (gw == F_IN){
    float s = 0.f;
#pragma unroll
    for (int i=0;i<8;i++){ int f=i*32+lane; s += bias[f]*phi[256+f]; }
    for (int o=16;o;o>>=1) s += __shfl_down_sync(0xFFFFFFFFu, s, o);
    if (!lane) g_c = s;
  }
}
__global__ void k_bvec(const float* __restrict__ x){
  __shared__ float su[F_IN];
  for (int i=threadIdx.x; i<F_IN; i+=256) su[i] = g_u[i];
  __syncthreads();
  int row = blockIdx.x*8 + (threadIdx.x >> 5);
  int lane = threadIdx.x & 31;
  const float* xr = x + (size_t)row*F_IN;
  float s = 0.f;
#pragma unroll
  for (int i=0;i<16;i++){ int k=i*32+lane; s += xr[k]*su[k]; }
  for (int o=16;o;o>>=1) s += __shfl_down_sync(0xFFFFFFFFu, s, o);
  if (!lane) g_b[row] = s + g_c;
}
__global__ void k_maxw(){
  __shared__ float s[1024];
  int t = threadIdx.x;
  float m = -3.4e38f;
  for (int i=t; i<N_NODES; i+=1024) m = fmaxf(m, g_b[i]);
  s[t] = m; __syncthreads();
  for (int o=512;o;o>>=1){ if (t<o) s[t]=fmaxf(s[t],s[t+o]); __syncthreads(); }
  float gm = s[0];
  for (int i=t; i<N_NODES; i+=1024) g_w[i] = expf(g_b[i] - gm);
}
__global__ void k_wht(const float* __restrict__ bias){
  __shared__ float s[32][33];
  int j0 = blockIdx.x*32, f0 = blockIdx.y*32;
  int tx = threadIdx.x & 31, ty = threadIdx.x >> 5;
  float bv = bias[f0+tx];
#pragma unroll
  for (int q=0;q<4;q++){
    size_t o = (size_t)(j0+ty+8*q)*F_OUT + f0+tx;
    s[ty+8*q][tx] = g_hp[o] + g_hp[o + (size_t)N_NODES*F_OUT] + bv;
  }
  __syncthreads();
  float wj = g_w[j0+tx];
#pragma unroll
  for (int q=0;q<4;q++)
    g_wht[(size_t)(f0+ty+8*q)*N_NODES + j0+tx] = __float2half_rn(wj * s[tx][ty+8*q]);
}
__global__ void k_epi(float* __restrict__ out){
  int i = blockIdx.x, t = threadIdx.x;   // 128 threads, 2 elems each via float2
  float inv = 1.f / (g_den[i] + g_den[N_NODES + i]);
  size_t o = (size_t)i*F_OUT + t*2;
  float2 p0 = *(const float2*)(g_hp + o);
  float2 p1 = *(const float2*)(g_hp + o + (size_t)N_NODES*F_OUT);
  float2 r;
  r.x = fmaxf((p0.x + p1.x) * inv, 0.f);
  r.y = fmaxf((p0.y + p1.y) * inv, 0.f);
  *(float2*)(out + o) = r;
}

// ---------------- GEMM1 (BM=128, split-K x2, 4-stage, per-ktile fills; R14 shape) ----------------
__global__ void __launch_bounds__(512) k_gemm1(){
  const uint32_t Asb = sm_u32(dynsm);            // 4 * 16384
  const uint32_t Bsb = Asb + 65536;              // 4 * 32768
  const int t = threadIdx.x, bm = blockIdx.x & 63, kh = blockIdx.x >> 6;
  const int warp = t>>5, lane = t&31, wm = warp&1, wn = warp>>1, g = lane>>2, tg = lane&3;
  float acc[4][4][4] = {};
  const int KT = 8;
  const int ar0 = t>>3, ac0 = t&7;
  const int ar1 = (t+512)>>3, ac1 = (t+512)&7;
  const int br = t>>1, bc0 = (t&1)*4;
  auto fill = [&](int s, int kt){
    cp16(Asb + s*16384 + ar0*128 + ((ac0^(ar0&7))<<4),
         g_xh + (size_t)(bm*128+ar0)*512 + kt*64 + ac0*8);
    cp16(Asb + s*16384 + ar1*128 + ((ac1^(ar1&7))<<4),
         g_xh + (size_t)(bm*128+ar1)*512 + kt*64 + ac1*8);
    const __half* bsrc = g_wt + (size_t)br*K1 + kh*512 + kt*64;
#pragma unroll
    for (int i=0;i<4;i++)
      cp16(Bsb + s*32768 + br*128 + (((bc0+i)^(br&7))<<4), bsrc + (bc0+i)*8);
  };
  fill(0,0); cpcommit();
  fill(1,1); cpcommit();
  for (int kt=0; kt<KT; kt++){
    if (kt+2 < KT){ fill((kt+2)&3, kt+2); cpcommit(); cpwaitg<2>(); }
    else cpwaitg<0>();
    __syncthreads();
    int s = kt&3;
    mma_tileW(Asb + s*16384, Bsb + s*32768, acc, wm, wn, lane);
  }
  float* hp = g_hp + (size_t)kh*N_NODES*F_OUT;
#pragma unroll
  for (int mi=0; mi<4; mi++)
#pragma unroll
    for (int ni=0; ni<4; ni++){
      int r = wm*64 + mi*16 + g, c = wn*32 + ni*8 + tg*2;
      size_t go = (size_t)(bm*128+r)*F_OUT + c;
      *(float2*)(hp+go)         = make_float2(acc[mi][ni][0], acc[mi][ni][1]);
      *(float2*)(hp+go+8*F_OUT) = make_float2(acc[mi][ni][2], acc[mi][ni][3]);
    }
}

// ---------------- GEMM2 (BM=128, split-K x2, 4-stage, 2-ktile periods; R14 shape, wsm dropped) ----------------
__global__ void __launch_bounds__(512) k_gemm2(const int* __restrict__ adj){
  const uint32_t Asb = sm_u32(dynsm);            // 4 * 16384
  const uint32_t Bsb = Asb + 65536;              // 4 * 32768
  __shared__ float sred[128][16];
  __shared__ float sden[128];
  const int t = threadIdx.x, bm = blockIdx.x & 63, kh = blockIdx.x >> 6;
  const int warp = t>>5, lane = t&31, wm = warp&1, wn = warp>>1, g = lane>>2, tg = lane&3;
  float acc[4][4][4] = {};
  float dpart[4] = {0.f,0.f,0.f,0.f};
  const int khoff = kh*4096;
  const int br = t>>1, bc0 = (t&1)*4;
  auto fillB = [&](int s, int kt){
    const __half* bsrc = g_wht + (size_t)br*N_NODES + khoff + kt*64;
#pragma unroll
    for (int i=0;i<4;i++)
      cp16(Bsb + s*32768 + br*128 + (((bc0+i)^(br&7))<<4), bsrc + (bc0+i)*8);
  };
  // A slots: 128 rows x 16 int4 = 2048, 4/thread
  int row_[4], c4_[4], gi_[4];
  const int4* aptr[4];
  uint32_t hdst[4];
#pragma unroll
  for (int i=0;i<4;i++){
    int slot = t + i*512;
    row_[i] = slot >> 4; c4_[i] = slot & 15;
    gi_[i] = bm*128 + row_[i];
    aptr[i] = (const int4*)(adj + (size_t)gi_[i]*N_NODES + khoff) + c4_[i];
    hdst[i] = Asb + row_[i]*128 + (((c4_[i]>>1) ^ (row_[i]&7)) << 4) + (c4_[i]&1)*8;
  }
  auto buildA = [&](int s, int c, const int4* av){
#pragma unroll
    for (int i=0;i<4;i++){
      int j = khoff + c*64 + c4_[i]*4;
      int4 a = av[i];
      int m0 = (a.x!=0) | (gi_[i]==j);
      int m1 = (a.y!=0) | (gi_[i]==j+1);
      int m2 = (a.z!=0) | (gi_[i]==j+2);
      int m3 = (a.w!=0) | (gi_[i]==j+3);
      float4 wv = *(const float4*)(g_w + khoff + c*64 + c4_[i]*4);   // L2-hot 32KB slice
      dpart[i] += (m0?wv.x:0.f) + (m1?wv.y:0.f) + (m2?wv.z:0.f) + (m3?wv.w:0.f);
      uint32_t u0 = (m0 ? 0x3C00u : 0u) | (m1 ? 0x3C000000u : 0u);
      uint32_t u1 = (m2 ? 0x3C00u : 0u) | (m3 ? 0x3C000000u : 0u);
      asm volatile("st.shared.v2.b32 [%0], {%1,%2};" :: "r"(hdst[i] + s*16384), "r"(u0), "r"(u1));
    }
  };
  const int KT = 64;
  int4 av[4];
#pragma unroll
  for (int i=0;i<4;i++) av[i] = aptr[i][0];
  buildA(0, 0, av);
#pragma unroll
  for (int i=0;i<4;i++) av[i] = aptr[i][16];
  buildA(1, 1, av);
#pragma unroll
  for (int i=0;i<4;i++) av[i] = aptr[i][32];   // bits for chunk 2
  fillB(0,0); cpcommit();
  fillB(1,1); cpcommit();
  for (int kt=0; kt<KT; kt+=2){
    if (kt+2 < KT){
      fillB((kt+2)&3, kt+2); cpcommit();
      fillB((kt+3)&3, kt+3); cpcommit();
      buildA((kt+2)&3, kt+2, av);        // av holds chunk kt+2
#pragma unroll
      for (int i=0;i<4;i++) av[i] = aptr[i][(kt+3)*16];   // LDG chunk kt+3 (lands under mma(kt))
      cpwaitg<2>();
    } else cpwaitg<0>();
    __syncthreads();
    mma_tileW(Asb + (kt&3)*16384, Bsb + (kt&3)*32768, acc, wm, wn, lane);
    if (kt+3 < KT){
      buildA((kt+3)&3, kt+3, av);        // hidden between the two mma halves
      if (kt+4 < KT){
#pragma unroll
        for (int i=0;i<4;i++) av[i] = aptr[i][(kt+4)*16]; // LDG chunk kt+4 (lands under mma(kt+1))
      }
    }
    mma_tileW(Asb + ((kt+1)&3)*16384, Bsb + ((kt+1)&3)*32768, acc, wm, wn, lane);
    __syncthreads();
  }
  // denominator partial reduction (16 partials per row)
#pragma unroll
  for (int i=0;i<4;i++) sred[row_[i]][c4_[i]] = dpart[i];
  __syncthreads();
  if (t < 128){
    float s = 0.f;
#pragma unroll
    for (int q=0;q<16;q++) s += sred[t][q];
    sden[t] = s;
    g_den[kh*N_NODES + bm*128 + t] = s;
  }
  __syncthreads();
  float* hp = g_hp + (size_t)kh*N_NODES*F_OUT;
#pragma unroll
  for (int mi=0; mi<4; mi++)
#pragma unroll
    for (int ni=0; ni<4; ni++){
      int r = wm*64 + mi*16 + g, c = wn*32 + ni*8 + tg*2;
      size_t go = (size_t)(bm*128+r)*F_OUT + c;
      *(float2*)(hp+go)         = make_float2(acc[mi][ni][0], acc[mi][ni][1]);
      *(float2*)(hp+go+8*F_OUT) = make_float2(acc[mi][ni][2], acc[mi][ni][3]);
    }
}

extern "C" void kernel_launch(void* const* d_in, const int* in_sizes, int n_in,
                              void* d_out, int out_size){
  const int*   adj  = (const int*)d_in[0];
  const float* x    = (const float*)d_in[1];
  const float* wgt  = (const float*)d_in[2];
  const float* bias = (const float*)d_in[3];
  const float* phi  = (const float*)d_in[4];
  float* out = (float*)d_out;
  cudaFuncSetAttribute(k_gemm1, cudaFuncAttributeMaxDynamicSharedMemorySize, 196608);
  cudaFuncSetAttribute(k_gemm2, cudaFuncAttributeMaxDynamicSharedMemorySize, 196608);
  k_conv<<<4608, 256>>>(x, wgt);              // 1
  k_ucc<<<65, 256>>>(wgt, bias, phi);         // 2
  k_bvec<<<N_NODES/8, 256>>>(x);              // 3
  k_gemm1<<<128, 512, 196608>>>();            // 4  <- ncu capture slot
  k_maxw<<<1, 1024>>>();                      // 5
  k_wht<<<dim3(256,8), 256>>>(bias);          // 6
  k_gemm2<<<128, 512, 196608>>>(adj);         // 7
  k_epi<<<N_NODES, 128>>>(out);               // 8
}